// round 6
// baseline (speedup 1.0000x reference)
#include <cuda_runtime.h>
#include <math.h>
#include <limits.h>

namespace {

constexpr int V  = 3;
constexpr int C  = 32;
constexpr int CD = 8;
constexpr int D  = 32;
constexpr int H  = 128;
constexpr int W  = 160;
constexpr int HW = H * W;
constexpr int KD = 8;            // depths per thread (4 f32x2 pairs)
constexpr float LAMB = 1.5f;
constexpr float EPSW = 1e-4f;    // wy snap threshold (fp32 noise ~1e-5)

__device__ float g_cost[D * HW];

typedef unsigned long long ull;
__device__ __forceinline__ ull pk2(float lo, float hi) {
    ull r; asm("mov.b64 %0,{%1,%2};" : "=l"(r) : "f"(lo), "f"(hi)); return r;
}
__device__ __forceinline__ void upk2(ull v, float& lo, float& hi) {
    asm("mov.b64 {%0,%1},%2;" : "=f"(lo), "=f"(hi) : "l"(v));
}
__device__ __forceinline__ ull fma2_(ull a, ull b, ull c) {
    ull d; asm("fma.rn.f32x2 %0,%1,%2,%3;" : "=l"(d) : "l"(a), "l"(b), "l"(c)); return d;
}
__device__ __forceinline__ ull mul2_(ull a, ull b) {
    ull d; asm("mul.rn.f32x2 %0,%1,%2;" : "=l"(d) : "l"(a), "l"(b)); return d;
}
__device__ __forceinline__ ull add2_(ull a, ull b) {
    ull d; asm("add.rn.f32x2 %0,%1,%2;" : "=l"(d) : "l"(a), "l"(b)); return d;
}

__device__ __forceinline__ void inv4x4(const float* m, float* inv) {
    inv[0]  =  m[5]*m[10]*m[15] - m[5]*m[11]*m[14] - m[9]*m[6]*m[15]
             + m[9]*m[7]*m[14] + m[13]*m[6]*m[11] - m[13]*m[7]*m[10];
    inv[4]  = -m[4]*m[10]*m[15] + m[4]*m[11]*m[14] + m[8]*m[6]*m[15]
             - m[8]*m[7]*m[14] - m[12]*m[6]*m[11] + m[12]*m[7]*m[10];
    inv[8]  =  m[4]*m[9]*m[15] - m[4]*m[11]*m[13] - m[8]*m[5]*m[15]
             + m[8]*m[7]*m[13] + m[12]*m[5]*m[11] - m[12]*m[7]*m[9];
    inv[12] = -m[4]*m[9]*m[14] + m[4]*m[10]*m[13] + m[8]*m[5]*m[14]
             - m[8]*m[6]*m[13] - m[12]*m[5]*m[10] + m[12]*m[6]*m[9];
    inv[1]  = -m[1]*m[10]*m[15] + m[1]*m[11]*m[14] + m[9]*m[2]*m[15]
             - m[9]*m[3]*m[14] - m[13]*m[2]*m[11] + m[13]*m[3]*m[10];
    inv[5]  =  m[0]*m[10]*m[15] - m[0]*m[11]*m[14] - m[8]*m[2]*m[15]
             + m[8]*m[3]*m[14] + m[12]*m[2]*m[11] - m[12]*m[3]*m[10];
    inv[9]  = -m[0]*m[9]*m[15] + m[0]*m[11]*m[13] + m[8]*m[1]*m[15]
             - m[8]*m[3]*m[13] - m[12]*m[1]*m[11] + m[12]*m[3]*m[9];
    inv[13] =  m[0]*m[9]*m[14] - m[0]*m[10]*m[13] - m[8]*m[1]*m[14]
             + m[8]*m[2]*m[13] + m[12]*m[1]*m[10] - m[12]*m[2]*m[9];
    inv[2]  =  m[1]*m[6]*m[15] - m[1]*m[7]*m[14] - m[5]*m[2]*m[15]
             + m[5]*m[3]*m[14] + m[13]*m[2]*m[7] - m[13]*m[3]*m[6];
    inv[6]  = -m[0]*m[6]*m[15] + m[0]*m[7]*m[14] + m[4]*m[2]*m[15]
             - m[4]*m[3]*m[14] - m[12]*m[2]*m[7] + m[12]*m[3]*m[6];
    inv[10] =  m[0]*m[5]*m[15] - m[0]*m[7]*m[13] - m[4]*m[1]*m[15]
             + m[4]*m[3]*m[13] + m[12]*m[1]*m[7] - m[12]*m[3]*m[5];
    inv[14] = -m[0]*m[5]*m[14] + m[0]*m[6]*m[13] + m[4]*m[1]*m[14]
             - m[4]*m[2]*m[13] - m[12]*m[1]*m[6] + m[12]*m[2]*m[5];
    inv[3]  = -m[1]*m[6]*m[11] + m[1]*m[7]*m[10] + m[5]*m[2]*m[11]
             - m[5]*m[3]*m[10] - m[9]*m[2]*m[7] + m[9]*m[3]*m[6];
    inv[7]  =  m[0]*m[6]*m[11] - m[0]*m[7]*m[10] - m[4]*m[2]*m[11]
             + m[4]*m[3]*m[10] + m[8]*m[2]*m[7] - m[8]*m[3]*m[6];
    inv[11] = -m[0]*m[5]*m[11] + m[0]*m[7]*m[9] + m[4]*m[1]*m[11]
             - m[4]*m[3]*m[9] - m[8]*m[1]*m[7] + m[8]*m[3]*m[5];
    inv[15] =  m[0]*m[5]*m[10] - m[0]*m[6]*m[9] - m[4]*m[1]*m[10]
             + m[4]*m[2]*m[9] + m[8]*m[1]*m[6] - m[8]*m[2]*m[5];
    float det = m[0]*inv[0] + m[1]*inv[4] + m[2]*inv[8] + m[3]*inv[12];
    float id = 1.0f / det;
    for (int i = 0; i < 16; i++) inv[i] *= id;
}

// ---------------------------------------------------------------------------
// Cost volume kernel. Block = 128 threads; warps never straddle image rows
// (W = 5*32). Fast path requires (runtime-checked, warp-uniform):
//   - wy within EPSW of 0/1 and sampled row == own row (pure x-shift),
//   - integer tap shift x0-x identical across the warp,
//   - total shift span <= 30.
// Then each warp stages 2x32 floats per view in REGISTERS and resolves every
// bilinear tap with variable-lane __shfl_sync (no SMEM, LSU = 5 LDG/channel).
// Variance math packed f32x2 over depth pairs. Fallback: exact 4-corner.
// ---------------------------------------------------------------------------
__global__ void __launch_bounds__(128) cost_kernel(
    const float* __restrict__ feat,    // (V, C, H, W)
    const float* __restrict__ deps,    // (V, CD, H, W)
    const float* __restrict__ dvals,   // (D, H, W)
    const float* __restrict__ regw,    // (40)
    const float* __restrict__ proj)    // (V, 4, 4)
{
    __shared__ float sM[2][12];
    __shared__ float sRW[C + CD];      // original weights (fallback)
    __shared__ float sRW2[C + CD];     // * 2/9 (fast path)

    if (threadIdx.x == 0) {
        float inv[16];
        inv4x4(proj, inv);
        for (int v = 1; v < V; v++) {
            const float* P = proj + v * 16;
            for (int r = 0; r < 3; r++)
                for (int c2 = 0; c2 < 4; c2++) {
                    float s = P[r*4+0]*inv[0*4+c2] + P[r*4+1]*inv[1*4+c2]
                            + P[r*4+2]*inv[2*4+c2] + P[r*4+3]*inv[3*4+c2];
                    if (c2 < 3) sM[v-1][r*3 + c2] = s;
                    else        sM[v-1][9 + r]    = s;
                }
        }
    }
    if (threadIdx.x < C + CD) {
        float wv = regw[threadIdx.x];
        sRW[threadIdx.x]  = wv;
        sRW2[threadIdx.x] = wv * (2.0f / 9.0f);
    }
    __syncthreads();

    const unsigned FULL = 0xFFFFFFFFu;
    const int tid  = threadIdx.x;
    const int lane = tid & 31;
    const int pix  = blockIdx.x * 128 + tid;
    const int d0   = blockIdx.y * KD;
    const int y    = pix / W;
    const int x    = pix - y * W;
    const int yW   = y * W;
    const float xf = (float)x, yf = (float)y;

    float wA[2][KD], wB[2][KD];       // per-(view,depth) tap weights
    int   u0[2][KD];                  // warp-uniform integer shift (x0 - x)
    bool  ok = true;

#pragma unroll
    for (int kd = 0; kd < KD; kd++) {
        const float dv = dvals[(d0 + kd) * HW + pix];
#pragma unroll
        for (int v = 0; v < 2; v++) {
            const float* M = sM[v];
            float r0 = M[0] * xf + M[1] * yf + M[2];
            float r1 = M[3] * xf + M[4] * yf + M[5];
            float r2 = M[6] * xf + M[7] * yf + M[8];
            float zx = r0 * dv + M[9];
            float zy = r1 * dv + M[10];
            float zz = r2 * dv + M[11];
            float iz = 1.0f / zz;
            float px = zx * iz;
            float py = zy * iz;

            float x0f = floorf(px), y0f = floorf(py);
            int   x0  = (int)x0f;
            int   y0  = (int)y0f;
            float wx = px - x0f, wy = py - y0f;
            bool  low = (wy <= EPSW);
            int   yr  = low ? y0 : (y0 + 1);
            float rowW = low ? (1.0f - wy) : wy;
            ok = ok && ((wy <= EPSW) || (wy >= 1.0f - EPSW)) && (yr == y);
            float vx0 = (x0 >= 0 && x0 < W) ? 1.0f : 0.0f;
            float vx1 = (x0 + 1 >= 0 && x0 + 1 < W) ? 1.0f : 0.0f;
            wA[v][kd] = (1.0f - wx) * rowW * vx0;
            wB[v][kd] = wx * rowW * vx1;

            int ul = x0 - x;                         // should be warp-uniform
            int ub = __shfl_sync(FULL, ul, 0);
            ok = ok && (ul == ub);
            u0[v][kd] = ub;
        }
    }

    // Per-view window base and per-depth delta (all warp-uniform values).
    int dlt[2][KD];
    int col0[2];
#pragma unroll
    for (int v = 0; v < 2; v++) {
        int mn = u0[v][0];
#pragma unroll
        for (int kd = 1; kd < KD; kd++) mn = min(mn, u0[v][kd]);
#pragma unroll
        for (int kd = 0; kd < KD; kd++) {
            int dl = u0[v][kd] - mn + 1;             // >= 1
            dlt[v][kd] = dl;
            ok = ok && (dl <= 30);                   // idx+1 <= 62
        }
        col0[v] = (x - lane) + mn - 1;               // window start column
    }
    const bool fast = __all_sync(FULL, ok);

    float costv[KD];

    if (fast) {
        // Staging load offsets (row-clamped; out-of-range taps have weight 0).
        int o00 = yW + min(max(col0[0] + lane,      0), W - 1);
        int o01 = yW + min(max(col0[0] + 32 + lane, 0), W - 1);
        int o10 = yW + min(max(col0[1] + lane,      0), W - 1);
        int o11 = yW + min(max(col0[1] + 32 + lane, 0), W - 1);

        ull COST[KD/2];
#pragma unroll
        for (int g = 0; g < KD/2; g++) COST[g] = 0ull;

        auto body = [&](const float* refp, const float* p1, const float* p2,
                        float w2) {
            float a0 = __ldg(p1 + o00), a1 = __ldg(p1 + o01);
            float b0 = __ldg(p2 + o10), b1 = __ldg(p2 + o11);
            float rv = __ldg(refp + pix);

            float s[2][KD];
#pragma unroll
            for (int kd = 0; kd < KD; kd++) {
                {
                    int idx = lane + dlt[0][kd];
                    float t0 = __shfl_sync(FULL, a0, idx);
                    float t1 = __shfl_sync(FULL, a1, idx);
                    float v0 = (idx & 32) ? t1 : t0;
                    int idx1 = idx + 1;
                    float q0 = __shfl_sync(FULL, a0, idx1);
                    float q1 = __shfl_sync(FULL, a1, idx1);
                    float v1 = (idx1 & 32) ? q1 : q0;
                    s[0][kd] = wA[0][kd] * v0 + wB[0][kd] * v1;
                }
                {
                    int idx = lane + dlt[1][kd];
                    float t0 = __shfl_sync(FULL, b0, idx);
                    float t1 = __shfl_sync(FULL, b1, idx);
                    float v0 = (idx & 32) ? t1 : t0;
                    int idx1 = idx + 1;
                    float q0 = __shfl_sync(FULL, b0, idx1);
                    float q1 = __shfl_sync(FULL, b1, idx1);
                    float v1 = (idx1 & 32) ? q1 : q0;
                    s[1][kd] = wA[1][kd] * v0 + wB[1][kd] * v1;
                }
            }

            ull RV  = pk2(rv, rv);
            ull RV2 = mul2_(RV, RV);
            ull WC  = pk2(w2, w2);
            ull WCn = pk2(-w2, -w2);
#pragma unroll
            for (int g = 0; g < KD/2; g++) {
                ull S1 = pk2(s[0][2*g], s[0][2*g+1]);
                ull S2 = pk2(s[1][2*g], s[1][2*g+1]);
                ull CR = fma2_(RV, add2_(S1, S2), mul2_(S1, S2));
                ull SF = fma2_(S2, S2, fma2_(S1, S1, RV2));
                COST[g] = fma2_(SF, WC,  COST[g]);
                COST[g] = fma2_(CR, WCn, COST[g]);
            }
        };

#pragma unroll 4
        for (int c = 0; c < C; c++)
            body(feat + c * HW, feat + (C + c) * HW, feat + (2 * C + c) * HW,
                 sRW2[c]);
#pragma unroll 4
        for (int c = 0; c < CD; c++)
            body(deps + c * HW, deps + (CD + c) * HW, deps + (2 * CD + c) * HW,
                 sRW2[C + c]);

#pragma unroll
        for (int g = 0; g < KD/2; g++)
            upk2(COST[g], costv[2*g], costv[2*g+1]);
    } else {
        // Exact 4-corner bilinear fallback (reference math), recomputed.
        int   lin[KD][2][4];
        float wt[KD][2][4];
#pragma unroll
        for (int kd = 0; kd < KD; kd++) {
            const float dv = dvals[(d0 + kd) * HW + pix];
#pragma unroll
            for (int v = 0; v < 2; v++) {
                const float* M = sM[v];
                float r0 = M[0] * xf + M[1] * yf + M[2];
                float r1 = M[3] * xf + M[4] * yf + M[5];
                float r2 = M[6] * xf + M[7] * yf + M[8];
                float zx = r0 * dv + M[9];
                float zy = r1 * dv + M[10];
                float zz = r2 * dv + M[11];
                float iz = 1.0f / zz;
                float px = zx * iz;
                float py = zy * iz;
                float x0f = floorf(px), y0f = floorf(py);
                int   x0  = (int)x0f,   y0  = (int)y0f;
                float wx = px - x0f, wy = py - y0f;
                float vx0 = (x0 >= 0  && x0 < W)        ? 1.0f : 0.0f;
                float vx1 = (x0 + 1 >= 0 && x0 + 1 < W) ? 1.0f : 0.0f;
                float vy0 = (y0 >= 0  && y0 < H)        ? 1.0f : 0.0f;
                float vy1 = (y0 + 1 >= 0 && y0 + 1 < H) ? 1.0f : 0.0f;
                wt[kd][v][0] = (1.0f - wx) * (1.0f - wy) * vx0 * vy0;
                wt[kd][v][1] = wx * (1.0f - wy) * vx1 * vy0;
                wt[kd][v][2] = (1.0f - wx) * wy * vx0 * vy1;
                wt[kd][v][3] = wx * wy * vx1 * vy1;
                int cx0 = min(max(x0, 0), W - 1);
                int cx1 = min(max(x0 + 1, 0), W - 1);
                int cy0 = min(max(y0, 0), H - 1);
                int cy1 = min(max(y0 + 1, 0), H - 1);
                lin[kd][v][0] = cy0 * W + cx0;
                lin[kd][v][1] = cy0 * W + cx1;
                lin[kd][v][2] = cy1 * W + cx0;
                lin[kd][v][3] = cy1 * W + cx1;
            }
        }
        constexpr float inv3 = 1.0f / 3.0f;
#pragma unroll
        for (int kd = 0; kd < KD; kd++) costv[kd] = 0.0f;
        for (int c = 0; c < C + CD; c++) {
            const float* base = (c < C) ? (feat + c * HW) : (deps + (c - C) * HW);
            const int    vstr = (c < C) ? (C * HW) : (CD * HW);
            const float rv = base[pix];
            const float* p1 = base + vstr;
            const float* p2 = base + 2 * vstr;
            const float wv = sRW[c];
#pragma unroll
            for (int kd = 0; kd < KD; kd++) {
                float s1 = p1[lin[kd][0][0]] * wt[kd][0][0]
                         + p1[lin[kd][0][1]] * wt[kd][0][1]
                         + p1[lin[kd][0][2]] * wt[kd][0][2]
                         + p1[lin[kd][0][3]] * wt[kd][0][3];
                float s2 = p2[lin[kd][1][0]] * wt[kd][1][0]
                         + p2[lin[kd][1][1]] * wt[kd][1][1]
                         + p2[lin[kd][1][2]] * wt[kd][1][2]
                         + p2[lin[kd][1][3]] * wt[kd][1][3];
                float s  = rv + s1 + s2;
                float sq = rv * rv + s1 * s1 + s2 * s2;
                float sm = s * inv3;
                costv[kd] += wv * (sq * inv3 - sm * sm);
            }
        }
    }

#pragma unroll
    for (int kd = 0; kd < KD; kd++)
        g_cost[(d0 + kd) * HW + pix] = costv[kd];
}

// ---------------------------------------------------------------------------
// Softmax over depth + moments. 4 threads cooperate per pixel (8 depths each)
// via quad shfl-xor reductions -> 2560 warps (vs 640) for latency hiding.
// ---------------------------------------------------------------------------
__global__ void __launch_bounds__(128) softmax_kernel(
    const float* __restrict__ dvals,   // (D, H, W)
    float* __restrict__ out)           // [depth HW | exp_var HW | prob D*HW]
{
    const unsigned FULL = 0xFFFFFFFFu;
    const int tid = threadIdx.x;
    const int sub = tid & 3;                 // depth-slice within pixel
    const int pix = blockIdx.x * 32 + (tid >> 2);

    float cv[8], dv[8];
#pragma unroll
    for (int j = 0; j < 8; j++) {
        int d = sub * 8 + j;
        cv[j] = g_cost[d * HW + pix];
        dv[j] = dvals[d * HW + pix];
    }

    float m = cv[0];
#pragma unroll
    for (int j = 1; j < 8; j++) m = fmaxf(m, cv[j]);
    m = fmaxf(m, __shfl_xor_sync(FULL, m, 1));
    m = fmaxf(m, __shfl_xor_sync(FULL, m, 2));

    float ssum = 0.0f;
#pragma unroll
    for (int j = 0; j < 8; j++) { cv[j] = expf(cv[j] - m); ssum += cv[j]; }
    ssum += __shfl_xor_sync(FULL, ssum, 1);
    ssum += __shfl_xor_sync(FULL, ssum, 2);
    const float isum = 1.0f / ssum;

    float depthv = 0.0f;
#pragma unroll
    for (int j = 0; j < 8; j++) {
        cv[j] *= isum;
        depthv += cv[j] * dv[j];
    }
    depthv += __shfl_xor_sync(FULL, depthv, 1);
    depthv += __shfl_xor_sync(FULL, depthv, 2);

    float var = 0.0f;
#pragma unroll
    for (int j = 0; j < 8; j++) {
        float t = dv[j] - depthv;
        var += cv[j] * t * t;
        out[2 * HW + (sub * 8 + j) * HW + pix] = cv[j];
    }
    var += __shfl_xor_sync(FULL, var, 1);
    var += __shfl_xor_sync(FULL, var, 2);

    if (sub == 0) {
        out[pix]      = depthv;
        out[HW + pix] = LAMB * sqrtf(var);
    }
}

} // namespace

extern "C" void kernel_launch(void* const* d_in, const int* in_sizes, int n_in,
                              void* d_out, int out_size) {
    const float* feat  = nullptr;
    const float* deps  = nullptr;
    const float* proj  = nullptr;
    const float* dvals = nullptr;
    const float* regw  = nullptr;
    for (int i = 0; i < n_in; i++) {
        switch (in_sizes[i]) {
            case V * C * HW:  feat  = (const float*)d_in[i]; break;
            case V * CD * HW: deps  = (const float*)d_in[i]; break;
            case V * 16:      proj  = (const float*)d_in[i]; break;
            case D * HW:      dvals = (const float*)d_in[i]; break;
            case C + CD:      regw  = (const float*)d_in[i]; break;
            default: break;
        }
    }
    float* out = (float*)d_out;

    dim3 grid(HW / 128, D / KD);
    cost_kernel<<<grid, 128>>>(feat, deps, dvals, regw, proj);
    softmax_kernel<<<HW * 4 / 128, 128>>>(dvals, out);
}

// round 7
// speedup vs baseline: 1.3801x; 1.3801x over previous
#include <cuda_runtime.h>
#include <math.h>

namespace {

constexpr int V  = 3;
constexpr int C  = 32;
constexpr int CD = 8;
constexpr int D  = 32;
constexpr int H  = 128;
constexpr int W  = 160;
constexpr int HW = H * W;
constexpr int KD = 8;            // depths per thread (one quarter of D)
constexpr float LAMB = 1.5f;
constexpr float EPSW = 1e-4f;    // wy snap threshold (fp32 noise ~1e-5)

typedef unsigned long long ull;
__device__ __forceinline__ ull pk2(float lo, float hi) {
    ull r; asm("mov.b64 %0,{%1,%2};" : "=l"(r) : "f"(lo), "f"(hi)); return r;
}
__device__ __forceinline__ void upk2(ull v, float& lo, float& hi) {
    asm("mov.b64 {%0,%1},%2;" : "=f"(lo), "=f"(hi) : "l"(v));
}
__device__ __forceinline__ ull fma2_(ull a, ull b, ull c) {
    ull d; asm("fma.rn.f32x2 %0,%1,%2,%3;" : "=l"(d) : "l"(a), "l"(b), "l"(c)); return d;
}
__device__ __forceinline__ ull mul2_(ull a, ull b) {
    ull d; asm("mul.rn.f32x2 %0,%1,%2;" : "=l"(d) : "l"(a), "l"(b)); return d;
}
__device__ __forceinline__ ull add2_(ull a, ull b) {
    ull d; asm("add.rn.f32x2 %0,%1,%2;" : "=l"(d) : "l"(a), "l"(b)); return d;
}

__device__ __forceinline__ void inv4x4(const float* m, float* inv) {
    inv[0]  =  m[5]*m[10]*m[15] - m[5]*m[11]*m[14] - m[9]*m[6]*m[15]
             + m[9]*m[7]*m[14] + m[13]*m[6]*m[11] - m[13]*m[7]*m[10];
    inv[4]  = -m[4]*m[10]*m[15] + m[4]*m[11]*m[14] + m[8]*m[6]*m[15]
             - m[8]*m[7]*m[14] - m[12]*m[6]*m[11] + m[12]*m[7]*m[10];
    inv[8]  =  m[4]*m[9]*m[15] - m[4]*m[11]*m[13] - m[8]*m[5]*m[15]
             + m[8]*m[7]*m[13] + m[12]*m[5]*m[11] - m[12]*m[7]*m[9];
    inv[12] = -m[4]*m[9]*m[14] + m[4]*m[10]*m[13] + m[8]*m[5]*m[14]
             - m[8]*m[6]*m[13] - m[12]*m[5]*m[10] + m[12]*m[6]*m[9];
    inv[1]  = -m[1]*m[10]*m[15] + m[1]*m[11]*m[14] + m[9]*m[2]*m[15]
             - m[9]*m[3]*m[14] - m[13]*m[2]*m[11] + m[13]*m[3]*m[10];
    inv[5]  =  m[0]*m[10]*m[15] - m[0]*m[11]*m[14] - m[8]*m[2]*m[15]
             + m[8]*m[3]*m[14] + m[12]*m[2]*m[11] - m[12]*m[3]*m[10];
    inv[9]  = -m[0]*m[9]*m[15] + m[0]*m[11]*m[13] + m[8]*m[1]*m[15]
             - m[8]*m[3]*m[13] - m[12]*m[1]*m[11] + m[12]*m[3]*m[9];
    inv[13] =  m[0]*m[9]*m[14] - m[0]*m[10]*m[13] - m[8]*m[1]*m[14]
             + m[8]*m[2]*m[13] + m[12]*m[1]*m[10] - m[12]*m[2]*m[9];
    inv[2]  =  m[1]*m[6]*m[15] - m[1]*m[7]*m[14] - m[5]*m[2]*m[15]
             + m[5]*m[3]*m[14] + m[13]*m[2]*m[7] - m[13]*m[3]*m[6];
    inv[6]  = -m[0]*m[6]*m[15] + m[0]*m[7]*m[14] + m[4]*m[2]*m[15]
             - m[4]*m[3]*m[14] - m[12]*m[2]*m[7] + m[12]*m[3]*m[6];
    inv[10] =  m[0]*m[5]*m[15] - m[0]*m[7]*m[13] - m[4]*m[1]*m[15]
             + m[4]*m[3]*m[13] + m[12]*m[1]*m[7] - m[12]*m[3]*m[5];
    inv[14] = -m[0]*m[5]*m[14] + m[0]*m[6]*m[13] + m[4]*m[1]*m[14]
             - m[4]*m[2]*m[13] - m[12]*m[1]*m[6] + m[12]*m[2]*m[5];
    inv[3]  = -m[1]*m[6]*m[11] + m[1]*m[7]*m[10] + m[5]*m[2]*m[11]
             - m[5]*m[3]*m[10] - m[9]*m[2]*m[7] + m[9]*m[3]*m[6];
    inv[7]  =  m[0]*m[6]*m[11] - m[0]*m[7]*m[10] - m[4]*m[2]*m[11]
             + m[4]*m[3]*m[10] + m[8]*m[2]*m[7] - m[8]*m[3]*m[6];
    inv[11] = -m[0]*m[5]*m[11] + m[0]*m[7]*m[9] + m[4]*m[1]*m[11]
             - m[4]*m[3]*m[9] - m[8]*m[1]*m[7] + m[8]*m[3]*m[5];
    inv[15] =  m[0]*m[5]*m[10] - m[0]*m[6]*m[9] - m[4]*m[1]*m[10]
             + m[4]*m[2]*m[9] + m[8]*m[1]*m[6] - m[8]*m[2]*m[5];
    float det = m[0]*inv[0] + m[1]*inv[4] + m[2]*inv[8] + m[3]*inv[12];
    float id = 1.0f / det;
    for (int i = 0; i < 16; i++) inv[i] *= id;
}

// ---------------------------------------------------------------------------
// Fully fused kernel. Block = 128 threads = 32 pixels x 4 depth-quarters
// (warp q owns depths q*8..q*8+7 of its 32 pixels). Cost volume fast path:
// per-warp SMEM float2 pair staging + LDS.64 taps (R5 engine, KD=8).
// Exact 4-corner GMEM fallback per warp. Softmax + moments fused via 3 SMEM
// exchange rounds across the 4 quarters. No global scratch, single launch.
// ---------------------------------------------------------------------------
__global__ void __launch_bounds__(128) depthnet_kernel(
    const float* __restrict__ feat,    // (V, C, H, W)
    const float* __restrict__ deps,    // (V, CD, H, W)
    const float* __restrict__ dvals,   // (D, H, W)
    const float* __restrict__ regw,    // (40)
    const float* __restrict__ proj,    // (V, 4, 4)
    float* __restrict__ out)           // [depth HW | exp_var HW | prob D*HW]
{
    __shared__ float  sM[2][12];
    __shared__ float  sRW[C + CD];         // original weights (fallback)
    __shared__ float  sRW2[C + CD];        // * 2/9 (fast path)
    __shared__ float2 sPair[2][4][2][64];  // [buf][warp][view][pair]
    __shared__ float  sMx[4][32];
    __shared__ float2 sSP[4][32];
    __shared__ float  sVr[4][32];

    if (threadIdx.x == 0) {
        float inv[16];
        inv4x4(proj, inv);
        for (int v = 1; v < V; v++) {
            const float* P = proj + v * 16;
            for (int r = 0; r < 3; r++)
                for (int c2 = 0; c2 < 4; c2++) {
                    float s = P[r*4+0]*inv[0*4+c2] + P[r*4+1]*inv[1*4+c2]
                            + P[r*4+2]*inv[2*4+c2] + P[r*4+3]*inv[3*4+c2];
                    if (c2 < 3) sM[v-1][r*3 + c2] = s;
                    else        sM[v-1][9 + r]    = s;
                }
        }
    }
    if (threadIdx.x < C + CD) {
        float wv = regw[threadIdx.x];
        sRW[threadIdx.x]  = wv;
        sRW2[threadIdx.x] = wv * (2.0f / 9.0f);
    }
    __syncthreads();

    const unsigned FULL = 0xFFFFFFFFu;
    const int tid  = threadIdx.x;
    const int lane = tid & 31;
    const int wrp  = tid >> 5;             // depth quarter 0..3
    const int pix  = blockIdx.x * 32 + lane;
    const int d0   = wrp * KD;
    const int y    = pix / W;
    const int x    = pix - y * W;
    const int yW   = y * W;
    const float xf = (float)x, yf = (float)y;

    float dv[KD];
    float wA[2][KD], wB[2][KD];
    int   u0[2][KD];
    bool  ok = true;

#pragma unroll
    for (int kd = 0; kd < KD; kd++) {
        dv[kd] = dvals[(d0 + kd) * HW + pix];
#pragma unroll
        for (int v = 0; v < 2; v++) {
            const float* M = sM[v];
            float r0 = M[0] * xf + M[1] * yf + M[2];
            float r1 = M[3] * xf + M[4] * yf + M[5];
            float r2 = M[6] * xf + M[7] * yf + M[8];
            float zx = r0 * dv[kd] + M[9];
            float zy = r1 * dv[kd] + M[10];
            float zz = r2 * dv[kd] + M[11];
            float iz = 1.0f / zz;
            float px = zx * iz;
            float py = zy * iz;

            float x0f = floorf(px), y0f = floorf(py);
            int   x0  = (int)x0f;
            int   y0  = (int)y0f;
            float wx = px - x0f, wy = py - y0f;
            bool  low = (wy <= EPSW);
            int   yr  = low ? y0 : (y0 + 1);
            float rowW = low ? (1.0f - wy) : wy;
            ok = ok && ((wy <= EPSW) || (wy >= 1.0f - EPSW)) && (yr == y);
            float vx0 = (x0 >= 0 && x0 < W) ? 1.0f : 0.0f;
            float vx1 = (x0 + 1 >= 0 && x0 + 1 < W) ? 1.0f : 0.0f;
            wA[v][kd] = (1.0f - wx) * rowW * vx0;
            wB[v][kd] = wx * rowW * vx1;

            int ul = x0 - x;                     // must be warp-uniform
            int ub = __shfl_sync(FULL, ul, 0);
            ok = ok && (ul == ub);
            u0[v][kd] = ub;
        }
    }

    int ls[2][KD];        // lane + per-depth delta into the staged pair table
    int col0[2];
#pragma unroll
    for (int v = 0; v < 2; v++) {
        int mn = u0[v][0];
#pragma unroll
        for (int kd = 1; kd < KD; kd++) mn = min(mn, u0[v][kd]);
#pragma unroll
        for (int kd = 0; kd < KD; kd++) {
            int dl = u0[v][kd] - mn + 1;
            ls[v][kd] = lane + dl;
            ok = ok && (dl <= 30);
        }
        col0[v] = (x - lane) + mn - 1;
    }
    const bool fast = __all_sync(FULL, ok);

    float costv[KD];

    if (fast) {
        const int o00 = yW + min(max(col0[0] + lane,      0), W - 1);
        const int o01 = yW + min(max(col0[0] + 32 + lane, 0), W - 1);
        const int o10 = yW + min(max(col0[1] + lane,      0), W - 1);
        const int o11 = yW + min(max(col0[1] + 32 + lane, 0), W - 1);

        ull COST[KD/2] = {0ull, 0ull, 0ull, 0ull};

        auto body = [&](const float* refp, const float* p1, const float* p2,
                        float w2, int buf) {
            float a0 = __ldg(p1 + o00), a1 = __ldg(p1 + o01);
            float b0 = __ldg(p2 + o10), b1 = __ldg(p2 + o11);
            float rv = __ldg(refp + pix);

            float ay = __shfl_sync(FULL, a0, (lane + 1) & 31);
            float ax = __shfl_sync(FULL, a1, 0);
            if (lane == 31) ay = ax;
            float az = __shfl_sync(FULL, a1, (lane + 1) & 31);  // pair 63 unused
            float by = __shfl_sync(FULL, b0, (lane + 1) & 31);
            float bx = __shfl_sync(FULL, b1, 0);
            if (lane == 31) by = bx;
            float bz = __shfl_sync(FULL, b1, (lane + 1) & 31);

            sPair[buf][wrp][0][lane]      = make_float2(a0, ay);
            sPair[buf][wrp][0][32 + lane] = make_float2(a1, az);
            sPair[buf][wrp][1][lane]      = make_float2(b0, by);
            sPair[buf][wrp][1][32 + lane] = make_float2(b1, bz);
            __syncwarp();

            const float2* sp0 = sPair[buf][wrp][0];
            const float2* sp1 = sPair[buf][wrp][1];
            float s1[KD], s2[KD];
#pragma unroll
            for (int kd = 0; kd < KD; kd++) {
                float2 t0 = sp0[ls[0][kd]];
                float2 t1 = sp1[ls[1][kd]];
                s1[kd] = wA[0][kd] * t0.x + wB[0][kd] * t0.y;
                s2[kd] = wA[1][kd] * t1.x + wB[1][kd] * t1.y;
            }

            ull RV  = pk2(rv, rv);
            ull RV2 = mul2_(RV, RV);
            ull WC  = pk2(w2, w2);
            ull WCn = pk2(-w2, -w2);
#pragma unroll
            for (int g = 0; g < KD/2; g++) {
                ull S1 = pk2(s1[2*g], s1[2*g+1]);
                ull S2 = pk2(s2[2*g], s2[2*g+1]);
                ull CR = fma2_(RV, add2_(S1, S2), mul2_(S1, S2));
                ull SF = fma2_(S2, S2, fma2_(S1, S1, RV2));
                COST[g] = fma2_(SF, WC,  COST[g]);
                COST[g] = fma2_(CR, WCn, COST[g]);
            }
        };

#pragma unroll 4
        for (int c = 0; c < C; c++)
            body(feat + c * HW, feat + (C + c) * HW, feat + (2 * C + c) * HW,
                 sRW2[c], c & 1);
#pragma unroll 4
        for (int c = 0; c < CD; c++)
            body(deps + c * HW, deps + (CD + c) * HW, deps + (2 * CD + c) * HW,
                 sRW2[C + c], c & 1);

#pragma unroll
        for (int g = 0; g < KD/2; g++)
            upk2(COST[g], costv[2*g], costv[2*g+1]);
    } else {
        // Exact 4-corner bilinear fallback (reference math).
        int   lin[KD][2][4];
        float wt[KD][2][4];
#pragma unroll
        for (int kd = 0; kd < KD; kd++) {
#pragma unroll
            for (int v = 0; v < 2; v++) {
                const float* M = sM[v];
                float r0 = M[0] * xf + M[1] * yf + M[2];
                float r1 = M[3] * xf + M[4] * yf + M[5];
                float r2 = M[6] * xf + M[7] * yf + M[8];
                float zx = r0 * dv[kd] + M[9];
                float zy = r1 * dv[kd] + M[10];
                float zz = r2 * dv[kd] + M[11];
                float iz = 1.0f / zz;
                float px = zx * iz;
                float py = zy * iz;
                float x0f = floorf(px), y0f = floorf(py);
                int   x0  = (int)x0f,   y0  = (int)y0f;
                float wx = px - x0f, wy = py - y0f;
                float vx0 = (x0 >= 0  && x0 < W)        ? 1.0f : 0.0f;
                float vx1 = (x0 + 1 >= 0 && x0 + 1 < W) ? 1.0f : 0.0f;
                float vy0 = (y0 >= 0  && y0 < H)        ? 1.0f : 0.0f;
                float vy1 = (y0 + 1 >= 0 && y0 + 1 < H) ? 1.0f : 0.0f;
                wt[kd][v][0] = (1.0f - wx) * (1.0f - wy) * vx0 * vy0;
                wt[kd][v][1] = wx * (1.0f - wy) * vx1 * vy0;
                wt[kd][v][2] = (1.0f - wx) * wy * vx0 * vy1;
                wt[kd][v][3] = wx * wy * vx1 * vy1;
                int cx0 = min(max(x0, 0), W - 1);
                int cx1 = min(max(x0 + 1, 0), W - 1);
                int cy0 = min(max(y0, 0), H - 1);
                int cy1 = min(max(y0 + 1, 0), H - 1);
                lin[kd][v][0] = cy0 * W + cx0;
                lin[kd][v][1] = cy0 * W + cx1;
                lin[kd][v][2] = cy1 * W + cx0;
                lin[kd][v][3] = cy1 * W + cx1;
            }
        }
        constexpr float inv3 = 1.0f / 3.0f;
#pragma unroll
        for (int kd = 0; kd < KD; kd++) costv[kd] = 0.0f;
        for (int c = 0; c < C + CD; c++) {
            const float* base = (c < C) ? (feat + c * HW) : (deps + (c - C) * HW);
            const int    vstr = (c < C) ? (C * HW) : (CD * HW);
            const float rv = base[pix];
            const float* p1 = base + vstr;
            const float* p2 = base + 2 * vstr;
            const float wv = sRW[c];
#pragma unroll
            for (int kd = 0; kd < KD; kd++) {
                float s1 = p1[lin[kd][0][0]] * wt[kd][0][0]
                         + p1[lin[kd][0][1]] * wt[kd][0][1]
                         + p1[lin[kd][0][2]] * wt[kd][0][2]
                         + p1[lin[kd][0][3]] * wt[kd][0][3];
                float s2 = p2[lin[kd][1][0]] * wt[kd][1][0]
                         + p2[lin[kd][1][1]] * wt[kd][1][1]
                         + p2[lin[kd][1][2]] * wt[kd][1][2]
                         + p2[lin[kd][1][3]] * wt[kd][1][3];
                float s  = rv + s1 + s2;
                float sq = rv * rv + s1 * s1 + s2 * s2;
                float sm = s * inv3;
                costv[kd] += wv * (sq * inv3 - sm * sm);
            }
        }
    }

    // ---------------- fused softmax + moments across the 4 quarters --------
    float m8 = costv[0];
#pragma unroll
    for (int j = 1; j < KD; j++) m8 = fmaxf(m8, costv[j]);
    sMx[wrp][lane] = m8;
    __syncthreads();
    float m = fmaxf(fmaxf(sMx[0][lane], sMx[1][lane]),
                    fmaxf(sMx[2][lane], sMx[3][lane]));

    float S = 0.0f, P = 0.0f;
#pragma unroll
    for (int j = 0; j < KD; j++) {
        float e = expf(costv[j] - m);
        costv[j] = e;
        S += e;
        P += e * dv[j];
    }
    sSP[wrp][lane] = make_float2(S, P);
    __syncthreads();
    float St = 0.0f, Pt = 0.0f;
#pragma unroll
    for (int q = 0; q < 4; q++) {
        float2 sp = sSP[q][lane];
        St += sp.x;
        Pt += sp.y;
    }
    const float isum  = 1.0f / St;
    const float depthv = Pt * isum;

    float v8 = 0.0f;
#pragma unroll
    for (int j = 0; j < KD; j++) {
        float p = costv[j] * isum;
        out[2 * HW + (d0 + j) * HW + pix] = p;
        float t = dv[j] - depthv;
        v8 += p * t * t;
    }
    sVr[wrp][lane] = v8;
    __syncthreads();
    if (wrp == 0) {
        float var = sVr[0][lane] + sVr[1][lane] + sVr[2][lane] + sVr[3][lane];
        out[pix]      = depthv;
        out[HW + pix] = LAMB * sqrtf(var);
    }
}

} // namespace

extern "C" void kernel_launch(void* const* d_in, const int* in_sizes, int n_in,
                              void* d_out, int out_size) {
    const float* feat  = nullptr;
    const float* deps  = nullptr;
    const float* proj  = nullptr;
    const float* dvals = nullptr;
    const float* regw  = nullptr;
    for (int i = 0; i < n_in; i++) {
        switch (in_sizes[i]) {
            case V * C * HW:  feat  = (const float*)d_in[i]; break;
            case V * CD * HW: deps  = (const float*)d_in[i]; break;
            case V * 16:      proj  = (const float*)d_in[i]; break;
            case D * HW:      dvals = (const float*)d_in[i]; break;
            case C + CD:      regw  = (const float*)d_in[i]; break;
            default: break;
        }
    }
    float* out = (float*)d_out;

    depthnet_kernel<<<HW / 32, 128>>>(feat, deps, dvals, regw, proj, out);
}

// round 9
// speedup vs baseline: 1.4608x; 1.0585x over previous
#include <cuda_runtime.h>
#include <math.h>

namespace {

constexpr int V  = 3;
constexpr int C  = 32;
constexpr int CD = 8;
constexpr int D  = 32;
constexpr int H  = 128;
constexpr int W  = 160;
constexpr int HW = H * W;
constexpr int KD = 8;            // depths per thread (one quarter of D)
constexpr float LAMB = 1.5f;
constexpr float EPSW = 1e-4f;    // wy snap threshold (fp32 noise ~1e-5)

typedef unsigned long long ull;
__device__ __forceinline__ ull pk2(float lo, float hi) {
    ull r; asm("mov.b64 %0,{%1,%2};" : "=l"(r) : "f"(lo), "f"(hi)); return r;
}
__device__ __forceinline__ void upk2(ull v, float& lo, float& hi) {
    asm("mov.b64 {%0,%1},%2;" : "=f"(lo), "=f"(hi) : "l"(v));
}
__device__ __forceinline__ ull fma2_(ull a, ull b, ull c) {
    ull d; asm("fma.rn.f32x2 %0,%1,%2,%3;" : "=l"(d) : "l"(a), "l"(b), "l"(c)); return d;
}
__device__ __forceinline__ ull mul2_(ull a, ull b) {
    ull d; asm("mul.rn.f32x2 %0,%1,%2;" : "=l"(d) : "l"(a), "l"(b)); return d;
}
__device__ __forceinline__ ull add2_(ull a, ull b) {
    ull d; asm("add.rn.f32x2 %0,%1,%2;" : "=l"(d) : "l"(a), "l"(b)); return d;
}

__device__ __forceinline__ void inv4x4(const float* m, float* inv) {
    inv[0]  =  m[5]*m[10]*m[15] - m[5]*m[11]*m[14] - m[9]*m[6]*m[15]
             + m[9]*m[7]*m[14] + m[13]*m[6]*m[11] - m[13]*m[7]*m[10];
    inv[4]  = -m[4]*m[10]*m[15] + m[4]*m[11]*m[14] + m[8]*m[6]*m[15]
             - m[8]*m[7]*m[14] - m[12]*m[6]*m[11] + m[12]*m[7]*m[10];
    inv[8]  =  m[4]*m[9]*m[15] - m[4]*m[11]*m[13] - m[8]*m[5]*m[15]
             + m[8]*m[7]*m[13] + m[12]*m[5]*m[11] - m[12]*m[7]*m[9];
    inv[12] = -m[4]*m[9]*m[14] + m[4]*m[10]*m[13] + m[8]*m[5]*m[14]
             - m[8]*m[6]*m[13] - m[12]*m[5]*m[10] + m[12]*m[6]*m[9];
    inv[1]  = -m[1]*m[10]*m[15] + m[1]*m[11]*m[14] + m[9]*m[2]*m[15]
             - m[9]*m[3]*m[14] - m[13]*m[2]*m[11] + m[13]*m[3]*m[10];
    inv[5]  =  m[0]*m[10]*m[15] - m[0]*m[11]*m[14] - m[8]*m[2]*m[15]
             + m[8]*m[3]*m[14] + m[12]*m[2]*m[11] - m[12]*m[3]*m[10];
    inv[9]  = -m[0]*m[9]*m[15] + m[0]*m[11]*m[13] + m[8]*m[1]*m[15]
             - m[8]*m[3]*m[13] - m[12]*m[1]*m[11] + m[12]*m[3]*m[9];
    inv[13] =  m[0]*m[9]*m[14] - m[0]*m[10]*m[13] - m[8]*m[1]*m[14]
             + m[8]*m[2]*m[13] + m[12]*m[1]*m[10] - m[12]*m[2]*m[9];
    inv[2]  =  m[1]*m[6]*m[15] - m[1]*m[7]*m[14] - m[5]*m[2]*m[15]
             + m[5]*m[3]*m[14] + m[13]*m[2]*m[7] - m[13]*m[3]*m[6];
    inv[6]  = -m[0]*m[6]*m[15] + m[0]*m[7]*m[14] + m[4]*m[2]*m[15]
             - m[4]*m[3]*m[14] - m[12]*m[2]*m[7] + m[12]*m[3]*m[6];
    inv[10] =  m[0]*m[5]*m[15] - m[0]*m[7]*m[13] - m[4]*m[1]*m[15]
             + m[4]*m[3]*m[13] + m[12]*m[1]*m[7] - m[12]*m[3]*m[5];
    inv[14] = -m[0]*m[5]*m[14] + m[0]*m[6]*m[13] + m[4]*m[1]*m[14]
             - m[4]*m[2]*m[13] - m[12]*m[1]*m[6] + m[12]*m[2]*m[5];
    inv[3]  = -m[1]*m[6]*m[11] + m[1]*m[7]*m[10] + m[5]*m[2]*m[11]
             - m[5]*m[3]*m[10] - m[9]*m[2]*m[7] + m[9]*m[3]*m[6];
    inv[7]  =  m[0]*m[6]*m[11] - m[0]*m[7]*m[10] - m[4]*m[2]*m[11]
             + m[4]*m[3]*m[10] + m[8]*m[2]*m[7] - m[8]*m[3]*m[6];
    inv[11] = -m[0]*m[5]*m[11] + m[0]*m[7]*m[9] + m[4]*m[1]*m[11]
             - m[4]*m[3]*m[9] - m[8]*m[1]*m[7] + m[8]*m[3]*m[5];
    inv[15] =  m[0]*m[5]*m[10] - m[0]*m[6]*m[9] - m[4]*m[1]*m[10]
             + m[4]*m[2]*m[9] + m[8]*m[1]*m[6] - m[8]*m[2]*m[5];
    float det = m[0]*inv[0] + m[1]*inv[4] + m[2]*inv[8] + m[3]*inv[12];
    float id = 1.0f / det;
    for (int i = 0; i < 16; i++) inv[i] *= id;
}

// ---------------------------------------------------------------------------
// Fully fused kernel. Block = 128 threads = 32 pixels x 4 depth-quarters.
// Cost fast path: per-warp SMEM float2 pair staging + LDS.64 taps, f32x2
// variance math. Exact 4-corner GMEM fallback. Softmax + moments fused via
// SMEM exchange. Register-capped at 128 (4 blocks/SM) for occupancy.
// ---------------------------------------------------------------------------
__global__ void __launch_bounds__(128, 4) depthnet_kernel(
    const float* __restrict__ feat,    // (V, C, H, W)
    const float* __restrict__ deps,    // (V, CD, H, W)
    const float* __restrict__ dvals,   // (D, H, W)
    const float* __restrict__ regw,    // (40)
    const float* __restrict__ proj,    // (V, 4, 4)
    float* __restrict__ out)           // [depth HW | exp_var HW | prob D*HW]
{
    __shared__ float  sM[2][12];
    __shared__ float  sRW[C + CD];         // original weights (fallback)
    __shared__ float  sRW2[C + CD];        // * 2/9 (fast path)
    __shared__ float2 sPair[2][4][2][64];  // [buf][warp][view][pair]
    __shared__ float  sMx[4][32];
    __shared__ float2 sSP[4][32];
    __shared__ float  sVr[4][32];

    if (threadIdx.x == 0) {
        float inv[16];
        inv4x4(proj, inv);
        for (int v = 1; v < V; v++) {
            const float* P = proj + v * 16;
            for (int r = 0; r < 3; r++)
                for (int c2 = 0; c2 < 4; c2++) {
                    float s = P[r*4+0]*inv[0*4+c2] + P[r*4+1]*inv[1*4+c2]
                            + P[r*4+2]*inv[2*4+c2] + P[r*4+3]*inv[3*4+c2];
                    if (c2 < 3) sM[v-1][r*3 + c2] = s;
                    else        sM[v-1][9 + r]    = s;
                }
        }
    }
    if (threadIdx.x < C + CD) {
        float wv = regw[threadIdx.x];
        sRW[threadIdx.x]  = wv;
        sRW2[threadIdx.x] = wv * (2.0f / 9.0f);
    }
    __syncthreads();

    const unsigned FULL = 0xFFFFFFFFu;
    const int tid  = threadIdx.x;
    const int lane = tid & 31;
    const int wrp  = tid >> 5;             // depth quarter 0..3
    const int pix  = blockIdx.x * 32 + lane;
    const int d0   = wrp * KD;
    const int y    = pix / W;
    const int x    = pix - y * W;
    const int yW   = y * W;
    const float xf = (float)x, yf = (float)y;

    float wA[2][KD], wB[2][KD];
    int   u0[2][KD];
    bool  ok = true;

#pragma unroll
    for (int kd = 0; kd < KD; kd++) {
        const float dvk = dvals[(d0 + kd) * HW + pix];
#pragma unroll
        for (int v = 0; v < 2; v++) {
            const float* M = sM[v];
            float r0 = M[0] * xf + M[1] * yf + M[2];
            float r1 = M[3] * xf + M[4] * yf + M[5];
            float r2 = M[6] * xf + M[7] * yf + M[8];
            float zx = r0 * dvk + M[9];
            float zy = r1 * dvk + M[10];
            float zz = r2 * dvk + M[11];
            float iz = 1.0f / zz;
            float px = zx * iz;
            float py = zy * iz;

            float x0f = floorf(px), y0f = floorf(py);
            int   x0  = (int)x0f;
            int   y0  = (int)y0f;
            float wx = px - x0f, wy = py - y0f;
            bool  low = (wy <= EPSW);
            int   yr  = low ? y0 : (y0 + 1);
            float rowW = low ? (1.0f - wy) : wy;
            ok = ok && ((wy <= EPSW) || (wy >= 1.0f - EPSW)) && (yr == y);
            float vx0 = (x0 >= 0 && x0 < W) ? 1.0f : 0.0f;
            float vx1 = (x0 + 1 >= 0 && x0 + 1 < W) ? 1.0f : 0.0f;
            wA[v][kd] = (1.0f - wx) * rowW * vx0;
            wB[v][kd] = wx * rowW * vx1;

            int ul = x0 - x;                     // must be warp-uniform
            int ub = __shfl_sync(FULL, ul, 0);
            ok = ok && (ul == ub);
            u0[v][kd] = ub;
        }
    }

    int ls[2][KD];        // lane + per-depth delta into the staged pair table
    int col0[2];
#pragma unroll
    for (int v = 0; v < 2; v++) {
        int mn = u0[v][0];
#pragma unroll
        for (int kd = 1; kd < KD; kd++) mn = min(mn, u0[v][kd]);
#pragma unroll
        for (int kd = 0; kd < KD; kd++) {
            int dl = u0[v][kd] - mn + 1;
            ls[v][kd] = lane + dl;
            ok = ok && (dl <= 30);
        }
        col0[v] = (x - lane) + mn - 1;
    }
    const bool fast = __all_sync(FULL, ok);

    float costv[KD];

    if (fast) {
        const int o00 = yW + min(max(col0[0] + lane,      0), W - 1);
        const int o01 = yW + min(max(col0[0] + 32 + lane, 0), W - 1);
        const int o10 = yW + min(max(col0[1] + lane,      0), W - 1);
        const int o11 = yW + min(max(col0[1] + 32 + lane, 0), W - 1);

        ull COST[KD/2] = {0ull, 0ull, 0ull, 0ull};

        auto body = [&](const float* refp, const float* p1, const float* p2,
                        float w2, int buf) {
            float a0 = __ldg(p1 + o00), a1 = __ldg(p1 + o01);
            float b0 = __ldg(p2 + o10), b1 = __ldg(p2 + o11);
            float rv = __ldg(refp + pix);

            float ay = __shfl_sync(FULL, a0, (lane + 1) & 31);
            float ax = __shfl_sync(FULL, a1, 0);
            if (lane == 31) ay = ax;
            float az = __shfl_sync(FULL, a1, (lane + 1) & 31);  // pair 63 unused
            float by = __shfl_sync(FULL, b0, (lane + 1) & 31);
            float bx = __shfl_sync(FULL, b1, 0);
            if (lane == 31) by = bx;
            float bz = __shfl_sync(FULL, b1, (lane + 1) & 31);

            sPair[buf][wrp][0][lane]      = make_float2(a0, ay);
            sPair[buf][wrp][0][32 + lane] = make_float2(a1, az);
            sPair[buf][wrp][1][lane]      = make_float2(b0, by);
            sPair[buf][wrp][1][32 + lane] = make_float2(b1, bz);
            __syncwarp();

            const float2* sp0 = sPair[buf][wrp][0];
            const float2* sp1 = sPair[buf][wrp][1];
            float s1[KD], s2[KD];
#pragma unroll
            for (int kd = 0; kd < KD; kd++) {
                float2 t0 = sp0[ls[0][kd]];
                float2 t1 = sp1[ls[1][kd]];
                s1[kd] = wA[0][kd] * t0.x + wB[0][kd] * t0.y;
                s2[kd] = wA[1][kd] * t1.x + wB[1][kd] * t1.y;
            }

            ull RV  = pk2(rv, rv);
            ull RV2 = mul2_(RV, RV);
            ull WC  = pk2(w2, w2);
            ull WCn = pk2(-w2, -w2);
#pragma unroll
            for (int g = 0; g < KD/2; g++) {
                ull S1 = pk2(s1[2*g], s1[2*g+1]);
                ull S2 = pk2(s2[2*g], s2[2*g+1]);
                ull CR = fma2_(RV, add2_(S1, S2), mul2_(S1, S2));
                ull SF = fma2_(S2, S2, fma2_(S1, S1, RV2));
                COST[g] = fma2_(SF, WC,  COST[g]);
                COST[g] = fma2_(CR, WCn, COST[g]);
            }
        };

#pragma unroll 2
        for (int c = 0; c < C; c++)
            body(feat + c * HW, feat + (C + c) * HW, feat + (2 * C + c) * HW,
                 sRW2[c], c & 1);
#pragma unroll 2
        for (int c = 0; c < CD; c++)
            body(deps + c * HW, deps + (CD + c) * HW, deps + (2 * CD + c) * HW,
                 sRW2[C + c], c & 1);

#pragma unroll
        for (int g = 0; g < KD/2; g++)
            upk2(COST[g], costv[2*g], costv[2*g+1]);
    } else {
        // Exact 4-corner bilinear fallback (reference math).
        int   lin[KD][2][4];
        float wt[KD][2][4];
#pragma unroll
        for (int kd = 0; kd < KD; kd++) {
            const float dvk = dvals[(d0 + kd) * HW + pix];
#pragma unroll
            for (int v = 0; v < 2; v++) {
                const float* M = sM[v];
                float r0 = M[0] * xf + M[1] * yf + M[2];
                float r1 = M[3] * xf + M[4] * yf + M[5];
                float r2 = M[6] * xf + M[7] * yf + M[8];
                float zx = r0 * dvk + M[9];
                float zy = r1 * dvk + M[10];
                float zz = r2 * dvk + M[11];
                float iz = 1.0f / zz;
                float px = zx * iz;
                float py = zy * iz;
                float x0f = floorf(px), y0f = floorf(py);
                int   x0  = (int)x0f,   y0  = (int)y0f;
                float wx = px - x0f, wy = py - y0f;
                float vx0 = (x0 >= 0  && x0 < W)        ? 1.0f : 0.0f;
                float vx1 = (x0 + 1 >= 0 && x0 + 1 < W) ? 1.0f : 0.0f;
                float vy0 = (y0 >= 0  && y0 < H)        ? 1.0f : 0.0f;
                float vy1 = (y0 + 1 >= 0 && y0 + 1 < H) ? 1.0f : 0.0f;
                wt[kd][v][0] = (1.0f - wx) * (1.0f - wy) * vx0 * vy0;
                wt[kd][v][1] = wx * (1.0f - wy) * vx1 * vy0;
                wt[kd][v][2] = (1.0f - wx) * wy * vx0 * vy1;
                wt[kd][v][3] = wx * wy * vx1 * vy1;
                int cx0 = min(max(x0, 0), W - 1);
                int cx1 = min(max(x0 + 1, 0), W - 1);
                int cy0 = min(max(y0, 0), H - 1);
                int cy1 = min(max(y0 + 1, 0), H - 1);
                lin[kd][v][0] = cy0 * W + cx0;
                lin[kd][v][1] = cy0 * W + cx1;
                lin[kd][v][2] = cy1 * W + cx0;
                lin[kd][v][3] = cy1 * W + cx1;
            }
        }
        constexpr float inv3 = 1.0f / 3.0f;
#pragma unroll
        for (int kd = 0; kd < KD; kd++) costv[kd] = 0.0f;
        for (int c = 0; c < C + CD; c++) {
            const float* base = (c < C) ? (feat + c * HW) : (deps + (c - C) * HW);
            const int    vstr = (c < C) ? (C * HW) : (CD * HW);
            const float rv = base[pix];
            const float* p1 = base + vstr;
            const float* p2 = base + 2 * vstr;
            const float wv = sRW[c];
#pragma unroll
            for (int kd = 0; kd < KD; kd++) {
                float s1 = p1[lin[kd][0][0]] * wt[kd][0][0]
                         + p1[lin[kd][0][1]] * wt[kd][0][1]
                         + p1[lin[kd][0][2]] * wt[kd][0][2]
                         + p1[lin[kd][0][3]] * wt[kd][0][3];
                float s2 = p2[lin[kd][1][0]] * wt[kd][1][0]
                         + p2[lin[kd][1][1]] * wt[kd][1][1]
                         + p2[lin[kd][1][2]] * wt[kd][1][2]
                         + p2[lin[kd][1][3]] * wt[kd][1][3];
                float s  = rv + s1 + s2;
                float sq = rv * rv + s1 * s1 + s2 * s2;
                float sm = s * inv3;
                costv[kd] += wv * (sq * inv3 - sm * sm);
            }
        }
    }

    // ---------------- fused softmax + moments across the 4 quarters --------
    float m8 = costv[0];
#pragma unroll
    for (int j = 1; j < KD; j++) m8 = fmaxf(m8, costv[j]);
    sMx[wrp][lane] = m8;
    __syncthreads();
    float m = fmaxf(fmaxf(sMx[0][lane], sMx[1][lane]),
                    fmaxf(sMx[2][lane], sMx[3][lane]));

    float dvr[KD];
#pragma unroll
    for (int j = 0; j < KD; j++) dvr[j] = dvals[(d0 + j) * HW + pix];

    float S = 0.0f, P = 0.0f;
#pragma unroll
    for (int j = 0; j < KD; j++) {
        float e = __expf(costv[j] - m);
        costv[j] = e;
        S += e;
        P += e * dvr[j];
    }
    sSP[wrp][lane] = make_float2(S, P);
    __syncthreads();
    float St = 0.0f, Pt = 0.0f;
#pragma unroll
    for (int q = 0; q < 4; q++) {
        float2 sp = sSP[q][lane];
        St += sp.x;
        Pt += sp.y;
    }
    const float isum  = 1.0f / St;
    const float depthv = Pt * isum;

    float v8 = 0.0f;
#pragma unroll
    for (int j = 0; j < KD; j++) {
        float p = costv[j] * isum;
        out[2 * HW + (d0 + j) * HW + pix] = p;
        float t = dvr[j] - depthv;
        v8 += p * t * t;
    }
    sVr[wrp][lane] = v8;
    __syncthreads();
    if (wrp == 0) {
        float var = sVr[0][lane] + sVr[1][lane] + sVr[2][lane] + sVr[3][lane];
        out[pix]      = depthv;
        out[HW + pix] = LAMB * sqrtf(var);
    }
}

} // namespace

extern "C" void kernel_launch(void* const* d_in, const int* in_sizes, int n_in,
                              void* d_out, int out_size) {
    const float* feat  = nullptr;
    const float* deps  = nullptr;
    const float* proj  = nullptr;
    const float* dvals = nullptr;
    const float* regw  = nullptr;
    for (int i = 0; i < n_in; i++) {
        switch (in_sizes[i]) {
            case V * C * HW:  feat  = (const float*)d_in[i]; break;
            case V * CD * HW: deps  = (const float*)d_in[i]; break;
            case V * 16:      proj  = (const float*)d_in[i]; break;
            case D * HW:      dvals = (const float*)d_in[i]; break;
            case C + CD:      regw  = (const float*)d_in[i]; break;
            default: break;
        }
    }
    float* out = (float*)d_out;

    depthnet_kernel<<<HW / 32, 128>>>(feat, deps, dvals, regw, proj, out);
}

// round 10
// speedup vs baseline: 1.5651x; 1.0714x over previous
#include <cuda_runtime.h>
#include <math.h>

namespace {

constexpr int V  = 3;
constexpr int C  = 32;
constexpr int CD = 8;
constexpr int D  = 32;
constexpr int H  = 128;
constexpr int W  = 160;
constexpr int HW = H * W;
constexpr int KD = 8;            // depths per thread (one quarter of D)
constexpr float LAMB = 1.5f;
constexpr float EPSW = 1e-4f;    // wy snap threshold (fp32 noise ~1e-5)

typedef unsigned long long ull;
__device__ __forceinline__ ull pk2(float lo, float hi) {
    ull r; asm("mov.b64 %0,{%1,%2};" : "=l"(r) : "f"(lo), "f"(hi)); return r;
}
__device__ __forceinline__ void upk2(ull v, float& lo, float& hi) {
    asm("mov.b64 {%0,%1},%2;" : "=f"(lo), "=f"(hi) : "l"(v));
}
__device__ __forceinline__ ull fma2_(ull a, ull b, ull c) {
    ull d; asm("fma.rn.f32x2 %0,%1,%2,%3;" : "=l"(d) : "l"(a), "l"(b), "l"(c)); return d;
}
__device__ __forceinline__ ull mul2_(ull a, ull b) {
    ull d; asm("mul.rn.f32x2 %0,%1,%2;" : "=l"(d) : "l"(a), "l"(b)); return d;
}
__device__ __forceinline__ ull add2_(ull a, ull b) {
    ull d; asm("add.rn.f32x2 %0,%1,%2;" : "=l"(d) : "l"(a), "l"(b)); return d;
}

__device__ __forceinline__ void inv4x4(const float* m, float* inv) {
    inv[0]  =  m[5]*m[10]*m[15] - m[5]*m[11]*m[14] - m[9]*m[6]*m[15]
             + m[9]*m[7]*m[14] + m[13]*m[6]*m[11] - m[13]*m[7]*m[10];
    inv[4]  = -m[4]*m[10]*m[15] + m[4]*m[11]*m[14] + m[8]*m[6]*m[15]
             - m[8]*m[7]*m[14] - m[12]*m[6]*m[11] + m[12]*m[7]*m[10];
    inv[8]  =  m[4]*m[9]*m[15] - m[4]*m[11]*m[13] - m[8]*m[5]*m[15]
             + m[8]*m[7]*m[13] + m[12]*m[5]*m[11] - m[12]*m[7]*m[9];
    inv[12] = -m[4]*m[9]*m[14] + m[4]*m[10]*m[13] + m[8]*m[5]*m[14]
             - m[8]*m[6]*m[13] - m[12]*m[5]*m[10] + m[12]*m[6]*m[9];
    inv[1]  = -m[1]*m[10]*m[15] + m[1]*m[11]*m[14] + m[9]*m[2]*m[15]
             - m[9]*m[3]*m[14] - m[13]*m[2]*m[11] + m[13]*m[3]*m[10];
    inv[5]  =  m[0]*m[10]*m[15] - m[0]*m[11]*m[14] - m[8]*m[2]*m[15]
             + m[8]*m[3]*m[14] + m[12]*m[2]*m[11] - m[12]*m[3]*m[10];
    inv[9]  = -m[0]*m[9]*m[15] + m[0]*m[11]*m[13] + m[8]*m[1]*m[15]
             - m[8]*m[3]*m[13] - m[12]*m[1]*m[11] + m[12]*m[3]*m[9];
    inv[13] =  m[0]*m[9]*m[14] - m[0]*m[10]*m[13] - m[8]*m[1]*m[14]
             + m[8]*m[2]*m[13] + m[12]*m[1]*m[10] - m[12]*m[2]*m[9];
    inv[2]  =  m[1]*m[6]*m[15] - m[1]*m[7]*m[14] - m[5]*m[2]*m[15]
             + m[5]*m[3]*m[14] + m[13]*m[2]*m[7] - m[13]*m[3]*m[6];
    inv[6]  = -m[0]*m[6]*m[15] + m[0]*m[7]*m[14] + m[4]*m[2]*m[15]
             - m[4]*m[3]*m[14] - m[12]*m[2]*m[7] + m[12]*m[3]*m[6];
    inv[10] =  m[0]*m[5]*m[15] - m[0]*m[7]*m[13] - m[4]*m[1]*m[15]
             + m[4]*m[3]*m[13] + m[12]*m[1]*m[7] - m[12]*m[3]*m[5];
    inv[14] = -m[0]*m[5]*m[14] + m[0]*m[6]*m[13] + m[4]*m[1]*m[14]
             - m[4]*m[2]*m[13] - m[12]*m[1]*m[6] + m[12]*m[2]*m[5];
    inv[3]  = -m[1]*m[6]*m[11] + m[1]*m[7]*m[10] + m[5]*m[2]*m[11]
             - m[5]*m[3]*m[10] - m[9]*m[2]*m[7] + m[9]*m[3]*m[6];
    inv[7]  =  m[0]*m[6]*m[11] - m[0]*m[7]*m[10] - m[4]*m[2]*m[11]
             + m[4]*m[3]*m[10] + m[8]*m[2]*m[7] - m[8]*m[3]*m[6];
    inv[11] = -m[0]*m[5]*m[11] + m[0]*m[7]*m[9] + m[4]*m[1]*m[11]
             - m[4]*m[3]*m[9] - m[8]*m[1]*m[7] + m[8]*m[3]*m[5];
    inv[15] =  m[0]*m[5]*m[10] - m[0]*m[6]*m[9] - m[4]*m[1]*m[10]
             + m[4]*m[2]*m[9] + m[8]*m[1]*m[6] - m[8]*m[2]*m[5];
    float det = m[0]*inv[0] + m[1]*inv[4] + m[2]*inv[8] + m[3]*inv[12];
    float id = 1.0f / det;
    for (int i = 0; i < 16; i++) inv[i] *= id;
}

// ---------------------------------------------------------------------------
// Fully fused kernel. Block = 128 threads = 32 pixels x 4 depth-quarters.
// Fast path: per-warp SMEM float2 pair staging + LDS.64 taps, f32x2 variance
// math. Exact 4-corner GMEM fallback (register-lean: no arrays, unroll 1 --
// it never runs on this geometry but preserves unconditional correctness).
// Softmax + moments fused via SMEM exchange. 5 blocks/SM -> grid 640 fits in
// ONE wave (capacity 740), eliminating the R9 wave-quantization tail.
// ---------------------------------------------------------------------------
__global__ void __launch_bounds__(128, 5) depthnet_kernel(
    const float* __restrict__ feat,    // (V, C, H, W)
    const float* __restrict__ deps,    // (V, CD, H, W)
    const float* __restrict__ dvals,   // (D, H, W)
    const float* __restrict__ regw,    // (40)
    const float* __restrict__ proj,    // (V, 4, 4)
    float* __restrict__ out)           // [depth HW | exp_var HW | prob D*HW]
{
    __shared__ float  sM[2][12];
    __shared__ float  sRW[C + CD];         // original weights (fallback)
    __shared__ float  sRW2[C + CD];        // * 2/9 (fast path)
    __shared__ float2 sPair[2][4][2][64];  // [buf][warp][view][pair]
    __shared__ float  sMx[4][32];
    __shared__ float2 sSP[4][32];
    __shared__ float  sVr[4][32];

    if (threadIdx.x == 0) {
        float inv[16];
        inv4x4(proj, inv);
        for (int v = 1; v < V; v++) {
            const float* P = proj + v * 16;
            for (int r = 0; r < 3; r++)
                for (int c2 = 0; c2 < 4; c2++) {
                    float s = P[r*4+0]*inv[0*4+c2] + P[r*4+1]*inv[1*4+c2]
                            + P[r*4+2]*inv[2*4+c2] + P[r*4+3]*inv[3*4+c2];
                    if (c2 < 3) sM[v-1][r*3 + c2] = s;
                    else        sM[v-1][9 + r]    = s;
                }
        }
    }
    if (threadIdx.x < C + CD) {
        float wv = regw[threadIdx.x];
        sRW[threadIdx.x]  = wv;
        sRW2[threadIdx.x] = wv * (2.0f / 9.0f);
    }
    __syncthreads();

    const unsigned FULL = 0xFFFFFFFFu;
    const int tid  = threadIdx.x;
    const int lane = tid & 31;
    const int wrp  = tid >> 5;             // depth quarter 0..3
    const int pix  = blockIdx.x * 32 + lane;
    const int d0   = wrp * KD;
    const int y    = pix / W;
    const int x    = pix - y * W;
    const int yW   = y * W;
    const float xf = (float)x, yf = (float)y;

    float wA[2][KD], wB[2][KD];
    int   u0[2][KD];
    bool  ok = true;

#pragma unroll
    for (int kd = 0; kd < KD; kd++) {
        const float dvk = dvals[(d0 + kd) * HW + pix];
#pragma unroll
        for (int v = 0; v < 2; v++) {
            const float* M = sM[v];
            float r0 = M[0] * xf + M[1] * yf + M[2];
            float r1 = M[3] * xf + M[4] * yf + M[5];
            float r2 = M[6] * xf + M[7] * yf + M[8];
            float zx = r0 * dvk + M[9];
            float zy = r1 * dvk + M[10];
            float zz = r2 * dvk + M[11];
            float iz = 1.0f / zz;
            float px = zx * iz;
            float py = zy * iz;

            float x0f = floorf(px), y0f = floorf(py);
            int   x0  = (int)x0f;
            int   y0  = (int)y0f;
            float wx = px - x0f, wy = py - y0f;
            bool  low = (wy <= EPSW);
            int   yr  = low ? y0 : (y0 + 1);
            float rowW = low ? (1.0f - wy) : wy;
            ok = ok && ((wy <= EPSW) || (wy >= 1.0f - EPSW)) && (yr == y);
            float vx0 = (x0 >= 0 && x0 < W) ? 1.0f : 0.0f;
            float vx1 = (x0 + 1 >= 0 && x0 + 1 < W) ? 1.0f : 0.0f;
            wA[v][kd] = (1.0f - wx) * rowW * vx0;
            wB[v][kd] = wx * rowW * vx1;

            int ul = x0 - x;                     // must be warp-uniform
            int ub = __shfl_sync(FULL, ul, 0);
            ok = ok && (ul == ub);
            u0[v][kd] = ub;
        }
    }

    int ls[2][KD];        // lane + per-depth delta into the staged pair table
    int col0[2];
#pragma unroll
    for (int v = 0; v < 2; v++) {
        int mn = u0[v][0];
#pragma unroll
        for (int kd = 1; kd < KD; kd++) mn = min(mn, u0[v][kd]);
#pragma unroll
        for (int kd = 0; kd < KD; kd++) {
            int dl = u0[v][kd] - mn + 1;
            ls[v][kd] = lane + dl;
            ok = ok && (dl <= 30);
        }
        col0[v] = (x - lane) + mn - 1;
    }
    const bool fast = __all_sync(FULL, ok);

    float costv[KD];

    if (fast) {
        const int o00 = yW + min(max(col0[0] + lane,      0), W - 1);
        const int o01 = yW + min(max(col0[0] + 32 + lane, 0), W - 1);
        const int o10 = yW + min(max(col0[1] + lane,      0), W - 1);
        const int o11 = yW + min(max(col0[1] + 32 + lane, 0), W - 1);

        ull COST[KD/2] = {0ull, 0ull, 0ull, 0ull};

        auto body = [&](const float* refp, const float* p1, const float* p2,
                        float w2, int buf) {
            float a0 = __ldg(p1 + o00), a1 = __ldg(p1 + o01);
            float b0 = __ldg(p2 + o10), b1 = __ldg(p2 + o11);
            float rv = __ldg(refp + pix);

            float ay = __shfl_sync(FULL, a0, (lane + 1) & 31);
            float ax = __shfl_sync(FULL, a1, 0);
            if (lane == 31) ay = ax;
            float az = __shfl_sync(FULL, a1, (lane + 1) & 31);  // pair 63 unused
            float by = __shfl_sync(FULL, b0, (lane + 1) & 31);
            float bx = __shfl_sync(FULL, b1, 0);
            if (lane == 31) by = bx;
            float bz = __shfl_sync(FULL, b1, (lane + 1) & 31);

            sPair[buf][wrp][0][lane]      = make_float2(a0, ay);
            sPair[buf][wrp][0][32 + lane] = make_float2(a1, az);
            sPair[buf][wrp][1][lane]      = make_float2(b0, by);
            sPair[buf][wrp][1][32 + lane] = make_float2(b1, bz);
            __syncwarp();

            const float2* sp0 = sPair[buf][wrp][0];
            const float2* sp1 = sPair[buf][wrp][1];
            float s1[KD], s2[KD];
#pragma unroll
            for (int kd = 0; kd < KD; kd++) {
                float2 t0 = sp0[ls[0][kd]];
                float2 t1 = sp1[ls[1][kd]];
                s1[kd] = wA[0][kd] * t0.x + wB[0][kd] * t0.y;
                s2[kd] = wA[1][kd] * t1.x + wB[1][kd] * t1.y;
            }

            ull RV  = pk2(rv, rv);
            ull RV2 = mul2_(RV, RV);
            ull WC  = pk2(w2, w2);
            ull WCn = pk2(-w2, -w2);
#pragma unroll
            for (int g = 0; g < KD/2; g++) {
                ull S1 = pk2(s1[2*g], s1[2*g+1]);
                ull S2 = pk2(s2[2*g], s2[2*g+1]);
                ull CR = fma2_(RV, add2_(S1, S2), mul2_(S1, S2));
                ull SF = fma2_(S2, S2, fma2_(S1, S1, RV2));
                COST[g] = fma2_(SF, WC,  COST[g]);
                COST[g] = fma2_(CR, WCn, COST[g]);
            }
        };

#pragma unroll 2
        for (int c = 0; c < C; c++)
            body(feat + c * HW, feat + (C + c) * HW, feat + (2 * C + c) * HW,
                 sRW2[c], c & 1);
#pragma unroll 2
        for (int c = 0; c < CD; c++)
            body(deps + c * HW, deps + (CD + c) * HW, deps + (2 * CD + c) * HW,
                 sRW2[C + c], c & 1);

#pragma unroll
        for (int g = 0; g < KD/2; g++)
            upk2(COST[g], costv[2*g], costv[2*g+1]);
    } else {
        // Exact 4-corner bilinear fallback (reference math). Register-lean:
        // one depth at a time, no arrays, outer loops not unrolled. This path
        // never executes for this problem's geometry; it exists only to keep
        // correctness unconditional.
        constexpr float inv3 = 1.0f / 3.0f;
#pragma unroll 1
        for (int kd = 0; kd < KD; kd++) {
            const float dvk = dvals[(d0 + kd) * HW + pix];
            int   lin[2][4];
            float wt[2][4];
#pragma unroll
            for (int v = 0; v < 2; v++) {
                const float* M = sM[v];
                float r0 = M[0] * xf + M[1] * yf + M[2];
                float r1 = M[3] * xf + M[4] * yf + M[5];
                float r2 = M[6] * xf + M[7] * yf + M[8];
                float zx = r0 * dvk + M[9];
                float zy = r1 * dvk + M[10];
                float zz = r2 * dvk + M[11];
                float iz = 1.0f / zz;
                float px = zx * iz;
                float py = zy * iz;
                float x0f = floorf(px), y0f = floorf(py);
                int   x0  = (int)x0f,   y0  = (int)y0f;
                float wx = px - x0f, wy = py - y0f;
                float vx0 = (x0 >= 0  && x0 < W)        ? 1.0f : 0.0f;
                float vx1 = (x0 + 1 >= 0 && x0 + 1 < W) ? 1.0f : 0.0f;
                float vy0 = (y0 >= 0  && y0 < H)        ? 1.0f : 0.0f;
                float vy1 = (y0 + 1 >= 0 && y0 + 1 < H) ? 1.0f : 0.0f;
                wt[v][0] = (1.0f - wx) * (1.0f - wy) * vx0 * vy0;
                wt[v][1] = wx * (1.0f - wy) * vx1 * vy0;
                wt[v][2] = (1.0f - wx) * wy * vx0 * vy1;
                wt[v][3] = wx * wy * vx1 * vy1;
                int cx0 = min(max(x0, 0), W - 1);
                int cx1 = min(max(x0 + 1, 0), W - 1);
                int cy0 = min(max(y0, 0), H - 1);
                int cy1 = min(max(y0 + 1, 0), H - 1);
                lin[v][0] = cy0 * W + cx0;
                lin[v][1] = cy0 * W + cx1;
                lin[v][2] = cy1 * W + cx0;
                lin[v][3] = cy1 * W + cx1;
            }
            float cost = 0.0f;
#pragma unroll 1
            for (int c = 0; c < C + CD; c++) {
                const float* base = (c < C) ? (feat + c * HW)
                                            : (deps + (c - C) * HW);
                const int    vstr = (c < C) ? (C * HW) : (CD * HW);
                const float rv = base[pix];
                const float* p1 = base + vstr;
                const float* p2 = base + 2 * vstr;
                float s1 = p1[lin[0][0]] * wt[0][0] + p1[lin[0][1]] * wt[0][1]
                         + p1[lin[0][2]] * wt[0][2] + p1[lin[0][3]] * wt[0][3];
                float s2 = p2[lin[1][0]] * wt[1][0] + p2[lin[1][1]] * wt[1][1]
                         + p2[lin[1][2]] * wt[1][2] + p2[lin[1][3]] * wt[1][3];
                float s  = rv + s1 + s2;
                float sq = rv * rv + s1 * s1 + s2 * s2;
                float sm = s * inv3;
                cost += sRW[c] * (sq * inv3 - sm * sm);
            }
            costv[kd] = cost;
        }
    }

    // ---------------- fused softmax + moments across the 4 quarters --------
    float m8 = costv[0];
#pragma unroll
    for (int j = 1; j < KD; j++) m8 = fmaxf(m8, costv[j]);
    sMx[wrp][lane] = m8;
    __syncthreads();
    float m = fmaxf(fmaxf(sMx[0][lane], sMx[1][lane]),
                    fmaxf(sMx[2][lane], sMx[3][lane]));

    float dvr[KD];
#pragma unroll
    for (int j = 0; j < KD; j++) dvr[j] = dvals[(d0 + j) * HW + pix];

    float S = 0.0f, P = 0.0f;
#pragma unroll
    for (int j = 0; j < KD; j++) {
        float e = __expf(costv[j] - m);
        costv[j] = e;
        S += e;
        P += e * dvr[j];
    }
    sSP[wrp][lane] = make_float2(S, P);
    __syncthreads();
    float St = 0.0f, Pt = 0.0f;
#pragma unroll
    for (int q = 0; q < 4; q++) {
        float2 sp = sSP[q][lane];
        St += sp.x;
        Pt += sp.y;
    }
    const float isum  = 1.0f / St;
    const float depthv = Pt * isum;

    float v8 = 0.0f;
#pragma unroll
    for (int j = 0; j < KD; j++) {
        float p = costv[j] * isum;
        out[2 * HW + (d0 + j) * HW + pix] = p;
        float t = dvr[j] - depthv;
        v8 += p * t * t;
    }
    sVr[wrp][lane] = v8;
    __syncthreads();
    if (wrp == 0) {
        float var = sVr[0][lane] + sVr[1][lane] + sVr[2][lane] + sVr[3][lane];
        out[pix]      = depthv;
        out[HW + pix] = LAMB * sqrtf(var);
    }
}

} // namespace

extern "C" void kernel_launch(void* const* d_in, const int* in_sizes, int n_in,
                              void* d_out, int out_size) {
    const float* feat  = nullptr;
    const float* deps  = nullptr;
    const float* proj  = nullptr;
    const float* dvals = nullptr;
    const float* regw  = nullptr;
    for (int i = 0; i < n_in; i++) {
        switch (in_sizes[i]) {
            case V * C * HW:  feat  = (const float*)d_in[i]; break;
            case V * CD * HW: deps  = (const float*)d_in[i]; break;
            case V * 16:      proj  = (const float*)d_in[i]; break;
            case D * HW:      dvals = (const float*)d_in[i]; break;
            case C + CD:      regw  = (const float*)d_in[i]; break;
            default: break;
        }
    }
    float* out = (float*)d_out;

    depthnet_kernel<<<HW / 32, 128>>>(feat, deps, dvals, regw, proj, out);
}